// round 15
// baseline (speedup 1.0000x reference)
#include <cuda_runtime.h>
#include <cuda_bf16.h>
#include <math.h>
#include <stdint.h>

#define Tdim 1653
#define TSP  1664
#define Ddim 512
#define Bdim 2
#define Edim 8
#define DE 64
#define BE 16
#define BT 3306
#define TDE (Tdim * DE)
#define KSPLIT 8
typedef __nv_bfloat16 bf16;
static const long long TT = (long long)Tdim * Tdim;

// ------------------- device scratch ------------------------------------------
__device__ __align__(16) float g_Y[3 * BT * Ddim];
__device__ __align__(16) float g_Wcat[3 * Ddim * Ddim];
__device__ __align__(16) float g_bcat[3 * Ddim];
__device__ __align__(16) float g_Q[BE * TDE], g_K[BE * TDE], g_V[BE * TDE];
__device__ __align__(16) float g_W2p[KSPLIT * BE * TDE];
__device__ __align__(16) float g_W2[BE * TDE];
__device__ __align__(16) float g_S[(long long)BE * Tdim * TSP];
__device__ __align__(16) float g_Op[KSPLIT * BE * TDE];
__device__ __align__(16) float g_O[BE * TDE];
__device__ __align__(16) float g_X[BT * Ddim];

// ------------------- helpers -------------------------------------------------
__device__ __forceinline__ uint32_t smem_u32(const void* p) {
    uint32_t a;
    asm("{ .reg .u64 t; cvta.to.shared.u64 t, %1; cvt.u32.u64 %0, t; }"
        : "=r"(a) : "l"(p));
    return a;
}
__device__ __forceinline__ void sp2(float v, bf16& h, bf16& l) {
    h = __float2bfloat16(v);
    l = __float2bfloat16(v - __bfloat162float(h));
}
__device__ __forceinline__ void ldm4(uint32_t* r, uint32_t a) {
    asm volatile("ldmatrix.sync.aligned.m8n8.x4.shared.b16 {%0,%1,%2,%3}, [%4];"
        : "=r"(r[0]), "=r"(r[1]), "=r"(r[2]), "=r"(r[3]) : "r"(a));
}
__device__ __forceinline__ void ldm4t(uint32_t* r, uint32_t a) {
    asm volatile("ldmatrix.sync.aligned.m8n8.x4.trans.shared.b16 {%0,%1,%2,%3}, [%4];"
        : "=r"(r[0]), "=r"(r[1]), "=r"(r[2]), "=r"(r[3]) : "r"(a));
}
__device__ __forceinline__ void mma16816(float* d, const uint32_t* a, const uint32_t* b) {
    asm volatile("mma.sync.aligned.m16n8k16.row.col.f32.bf16.bf16.f32 "
        "{%0,%1,%2,%3}, {%4,%5,%6,%7}, {%8,%9}, {%0,%1,%2,%3};"
        : "+f"(d[0]), "+f"(d[1]), "+f"(d[2]), "+f"(d[3])
        : "r"(a[0]), "r"(a[1]), "r"(a[2]), "r"(a[3]), "r"(b[0]), "r"(b[1]));
}
__device__ __forceinline__ void cpa16(float* d, const float* s) {
    asm volatile("cp.async.ca.shared.global [%0], [%1], 16;"
                 :: "r"(smem_u32(d)), "l"(s));
}
__device__ __forceinline__ void cpa4(float* d, const float* s) {
    asm volatile("cp.async.ca.shared.global [%0], [%1], 4;"
                 :: "r"(smem_u32(d)), "l"(s));
}
// alignment of a gmem float pointer, in floats (0..3)
__device__ __forceinline__ int falign(const float* p) {
    return (int)((((uintptr_t)p) >> 2) & 3);
}

// ---- cp.async prefetchers: fp32 gmem -> fp32 staging smem ----
// no-trans: 128 rows x 32 k, staging pitch 36
__device__ __forceinline__ void pf_nt(const float* __restrict__ src, int r0, int Rtot,
                                      int ld, int k0, int K, float* st)
{
    const int t = threadIdx.x;
    const int r = t >> 1, h = t & 1;
    const int kb = k0 + h * 16;
    float* d = st + r * 36 + h * 16;
    const float* s = src + (long long)(r0 + r) * ld + kb;
    if ((r0 + r) < Rtot) {
        const uint32_t da = smem_u32(d);
#pragma unroll
        for (int q = 0; q < 4; ++q) {
            const int rem = (K - (kb + q * 4)) * 4;
            if (rem >= 16) {
                asm volatile("cp.async.ca.shared.global [%0], [%1], 16;"
                             :: "r"(da + q * 16), "l"(s + q * 4));
            } else if (rem > 0) {
                asm volatile("cp.async.ca.shared.global [%0], [%1], 16, %2;"
                             :: "r"(da + q * 16), "l"(s + q * 4), "r"(rem));
            } else {
                *reinterpret_cast<float4*>(d + q * 4) = make_float4(0.f, 0.f, 0.f, 0.f);
            }
        }
    } else {
#pragma unroll
        for (int q = 0; q < 4; ++q)
            *reinterpret_cast<float4*>(d + q * 4) = make_float4(0.f, 0.f, 0.f, 0.f);
    }
}

// trans, VECTORIZED: 32 k-rows x C cols, staging pitch C+8; element c stored at
// smem offset a+c where a = TRUE gmem pointer alignment (incl. batch base).
template <int C, int ODD>
__device__ __forceinline__ void pf_tr(const float* __restrict__ src, int k0, int K,
                                      int c0, int Ctot, int ld, float* st)
{
    constexpr int PS = C + 8;
    const int t = threadIdx.x;
    const int kr = t >> 3;
    const int lane8 = t & 7;
    float* drow = st + kr * PS;
    const float* g = src + (long long)(k0 + kr) * ld + c0;
    const int a = ODD ? falign(g) : 0;
    const bool rowok = (k0 + kr) < K;
    if (rowok && c0 + C <= Ctot) {
        const int pad = (4 - a) & 3;
        const int nch = (C - pad) >> 2;
        if (ODD && lane8 == 0) {
            for (int q = 0; q < pad; ++q) cpa4(drow + a + q, g + q);
        }
        for (int ch = lane8; ch < nch; ch += 8)
            cpa16(drow + a + pad + ch * 4, g + pad + ch * 4);
        if (ODD && lane8 == 7) {
            for (int q = pad + nch * 4; q < C; ++q) cpa4(drow + a + q, g + q);
        }
    } else {
        for (int c = lane8; c < C; c += 8) {
            if (rowok && c0 + c < Ctot) cpa4(drow + a + c, g + c);
            else                        drow[a + c] = 0.f;
        }
    }
}

// ---- converters: fp32 staging -> bf16 hi/lo tiles ----
__device__ __forceinline__ void cvt_nt(const float* st, bf16* H, bf16* L)
{
    const int t = threadIdx.x;
    const int r = t >> 1, h = t & 1;
    const float* s = st + r * 36 + h * 16;
    bf16* hp = H + r * 40 + h * 16;
    bf16* lp = L + r * 40 + h * 16;
#pragma unroll
    for (int q = 0; q < 16; q += 2) {
        bf16 h0, l0, h1, l1;
        sp2(s[q], h0, l0); sp2(s[q + 1], h1, l1);
        __nv_bfloat162 hh; hh.x = h0; hh.y = h1;
        __nv_bfloat162 ll; ll.x = l0; ll.y = l1;
        *reinterpret_cast<__nv_bfloat162*>(hp + q) = hh;
        *reinterpret_cast<__nv_bfloat162*>(lp + q) = ll;
    }
}

template <int C, int P, int ODD>
__device__ __forceinline__ void cvt_tr(const float* st, bf16* H, bf16* L,
                                       const float* __restrict__ src,
                                       int k0, int ld, int c0)
{
    constexpr int PS = C + 8;
    constexpr int CW = C / 8;          // 16 or 8 cols per thread
    const int t = threadIdx.x;
    const int kr = t >> 3;
    const int cb = (t & 7) * CW;
    const int a = ODD ? falign(src + (long long)(k0 + kr) * ld + c0) : 0;
    const float* s = st + kr * PS + a + cb;
    bf16* hp = H + kr * P + cb;
    bf16* lp = L + kr * P + cb;
#pragma unroll
    for (int q = 0; q < CW; q += 2) {
        bf16 h0, l0, h1, l1;
        sp2(s[q], h0, l0); sp2(s[q + 1], h1, l1);
        __nv_bfloat162 hh; hh.x = h0; hh.y = h1;
        __nv_bfloat162 ll; ll.x = l0; ll.y = l1;
        *reinterpret_cast<__nv_bfloat162*>(hp + q) = hh;
        *reinterpret_cast<__nv_bfloat162*>(lp + q) = ll;
    }
}

// ------------------- pipelined split-bf16 tensor-core GEMM -------------------
// C[M,N] = A[M,K]*B^T (logical). TRA: A stored [k][m]; TRB: B stored [k][n].
// ODDA: A's effective base/stride can be unaligned (per-row handling).
// MODE 1: +bias ep[n]  MODE 2: *scale*ep[m*Tdim+n]  MODE 3: split-K partial
template <int BN, int TRA, int TRB, int MODE, int ODDA>
__global__ void __launch_bounds__(256, 2)
mma_gemm(const float* __restrict__ A, const float* __restrict__ B,
         float* __restrict__ C, int M, int N, int K,
         int lda, int ldb, int ldc,
         long long sA, long long sB, long long sC,
         const float* __restrict__ ep, long long sEp, float scale,
         int kItersPer, long long sKS)
{
    constexpr int PA  = TRA ? 136 : 40;
    constexpr int PB  = TRB ? (BN + 8) : 40;
    constexpr int ASZ = TRA ? 32 * 136 : 128 * 40;
    constexpr int BSZ = TRB ? 32 * (BN + 8) : BN * 40;
    constexpr int SAF = TRA ? 32 * 136 : 128 * 36;
    constexpr int SBF = TRB ? 32 * (BN + 8) : BN * 36;

    extern __shared__ __align__(16) char smraw[];
    float* stA0 = reinterpret_cast<float*>(smraw);
    float* stA1 = stA0 + SAF;
    float* stB0 = stA1 + SAF;
    float* stB1 = stB0 + SBF;
    bf16*  Ah   = reinterpret_cast<bf16*>(stB1 + SBF);
    bf16*  Al   = Ah + ASZ;
    bf16*  Bh   = Al + ASZ;
    bf16*  Bl   = Bh + BSZ;

    const int bz = blockIdx.z;
    A += (long long)bz * sA;
    B += (long long)bz * sB;
    C += (long long)bz * sC;
    if (MODE == 3) C += (long long)blockIdx.x * sKS;
    if (MODE == 1 || MODE == 2) ep += (long long)bz * sEp;

    const int m0 = blockIdx.y * 128;
    const int n0 = (MODE == 3) ? 0 : blockIdx.x * BN;
    const int tid = threadIdx.x, l = tid & 31, wid = tid >> 5;
    constexpr int WN = BN / 2;
    constexpr int NT = WN / 8;
    const int wm = wid & 3, wn = wid >> 2;
    const int rmw = wm * 32;
    const int nbw = wn * WN;

    float acc[2][NT][4];
#pragma unroll
    for (int i = 0; i < 2; ++i)
#pragma unroll
        for (int j = 0; j < NT; ++j)
#pragma unroll
            for (int q = 0; q < 4; ++q) acc[i][j][q] = 0.f;

    const uint32_t baseAh = smem_u32(Ah), baseAl = smem_u32(Al);
    const uint32_t baseBh = smem_u32(Bh), baseBl = smem_u32(Bl);
    uint32_t aoff, boff;
    if (TRA) aoff = (((l & 7) + ((l >> 4) << 3)) * PA + ((l >> 3) & 1) * 8) * 2;
    else     aoff = ((l & 15) * PA + (l >> 4) * 8) * 2;
    if (TRB) boff = (((l & 7) + (((l >> 3) & 1) << 3)) * PB + ((l >> 4) << 3)) * 2;
    else     boff = (((l & 7) + ((l >> 4) << 3)) * PB + ((l >> 3) & 1) * 8) * 2;

    const int kItersAll = (K + 31) / 32;
    int kt0 = 0, kt1 = kItersAll;
    if (MODE == 3) {
        kt0 = blockIdx.x * kItersPer;
        kt1 = min(kItersAll, kt0 + kItersPer);
    }

    auto prefetch = [&](int kt, int buf) {
        const int k0 = kt * 32;
        float* sa = buf ? stA1 : stA0;
        float* sb = buf ? stB1 : stB0;
        if (TRA) pf_tr<128, ODDA>(A, k0, K, m0, M, lda, sa);
        else     pf_nt(A, m0, M, lda, k0, K, sa);
        if (TRB) pf_tr<BN, 0>(B, k0, K, n0, N, ldb, sb);
        else     pf_nt(B, n0, N, ldb, k0, K, sb);
        asm volatile("cp.async.commit_group;" ::: "memory");
    };

    if (kt0 < kt1) {
        prefetch(kt0, 0);
        for (int kt = kt0; kt < kt1; ++kt) {
            const int cur = (kt - kt0) & 1;
            const int k0 = kt * 32;
            if (kt + 1 < kt1) {
                prefetch(kt + 1, cur ^ 1);
                asm volatile("cp.async.wait_group 1;" ::: "memory");
            } else {
                asm volatile("cp.async.wait_group 0;" ::: "memory");
            }
            __syncthreads();
            if (TRA) cvt_tr<128, 136, ODDA>(cur ? stA1 : stA0, Ah, Al, A, k0, lda, m0);
            else     cvt_nt(cur ? stA1 : stA0, Ah, Al);
            if (TRB) cvt_tr<BN, BN + 8, 0>(cur ? stB1 : stB0, Bh, Bl, B, k0, ldb, n0);
            else     cvt_nt(cur ? stB1 : stB0, Bh, Bl);
            __syncthreads();
#pragma unroll
            for (int ks = 0; ks < 2; ++ks) {
                uint32_t ah[2][4], al2[2][4];
#pragma unroll
                for (int mt = 0; mt < 2; ++mt) {
                    const int rm = rmw + mt * 16;
                    const uint32_t rel = TRA ? (uint32_t)((ks * 16 * PA + rm) * 2)
                                             : (uint32_t)((rm * PA + ks * 16) * 2);
                    if (TRA) { ldm4t(ah[mt], baseAh + rel + aoff); ldm4t(al2[mt], baseAl + rel + aoff); }
                    else     { ldm4 (ah[mt], baseAh + rel + aoff); ldm4 (al2[mt], baseAl + rel + aoff); }
                }
                uint32_t bh[NT][2], bl2[NT][2];
#pragma unroll
                for (int np = 0; np < NT / 2; ++np) {
                    const int nb = nbw + np * 16;
                    const uint32_t rel = TRB ? (uint32_t)((ks * 16 * PB + nb) * 2)
                                             : (uint32_t)((nb * PB + ks * 16) * 2);
                    uint32_t rh[4], rl[4];
                    if (TRB) { ldm4t(rh, baseBh + rel + boff); ldm4t(rl, baseBl + rel + boff); }
                    else     { ldm4 (rh, baseBh + rel + boff); ldm4 (rl, baseBl + rel + boff); }
                    bh[2 * np][0] = rh[0]; bh[2 * np][1] = rh[1];
                    bh[2 * np + 1][0] = rh[2]; bh[2 * np + 1][1] = rh[3];
                    bl2[2 * np][0] = rl[0]; bl2[2 * np][1] = rl[1];
                    bl2[2 * np + 1][0] = rl[2]; bl2[2 * np + 1][1] = rl[3];
                }
#pragma unroll
                for (int mt = 0; mt < 2; ++mt)
#pragma unroll
                    for (int nt = 0; nt < NT; ++nt) {
                        mma16816(acc[mt][nt], ah[mt],  bh[nt]);
                        mma16816(acc[mt][nt], ah[mt],  bl2[nt]);
                        mma16816(acc[mt][nt], al2[mt], bh[nt]);
                    }
            }
            __syncthreads();
        }
    }

#pragma unroll
    for (int mt = 0; mt < 2; ++mt)
#pragma unroll
        for (int nt = 0; nt < NT; ++nt)
#pragma unroll
            for (int half = 0; half < 2; ++half) {
                const int m = m0 + rmw + mt * 16 + (l >> 2) + half * 8;
                const int n = n0 + nbw + nt * 8 + (l & 3) * 2;
                if (m >= M) continue;
                float v0 = acc[mt][nt][half * 2 + 0];
                float v1 = acc[mt][nt][half * 2 + 1];
                if (MODE == 1) {
                    if (n < N)     v0 += ep[n];
                    if (n + 1 < N) v1 += ep[n + 1];
                }
                if (MODE == 2) {
                    if (n < N)     v0 *= scale * ep[(long long)m * Tdim + n];
                    if (n + 1 < N) v1 *= scale * ep[(long long)m * Tdim + n + 1];
                }
                if (n + 1 < N) {
                    *reinterpret_cast<float2*>(C + (long long)m * ldc + n) = make_float2(v0, v1);
                } else if (n < N) {
                    C[(long long)m * ldc + n] = v0;
                }
            }
}

// ------------------- elementwise kernels -------------------------------------
__global__ void pack_wb(const float* Wq, const float* Wk, const float* Wv,
                        const float* bq, const float* bk, const float* bv)
{
    const int i = blockIdx.x * 256 + threadIdx.x;
    const int WW = Ddim * Ddim;
    if (i < WW) {
        g_Wcat[i] = Wq[i];
        g_Wcat[WW + i] = Wk[i];
        g_Wcat[2 * WW + i] = Wv[i];
    }
    if (i < Ddim) {
        g_bcat[i] = bq[i];
        g_bcat[Ddim + i] = bk[i];
        g_bcat[2 * Ddim + i] = bv[i];
    }
}

__global__ void scatter_qkv()
{
    const int idx = blockIdx.x * 256 + threadIdx.x;
    if (idx >= BE * TDE) return;
    const int g = idx / TDE, f = idx % TDE;
    const int b = g >> 3, e = g & 7;
    const int tt = f % Tdim, j = f / Tdim;
    const long long src = (long long)(b * Tdim + tt) * Ddim + e * DE + j;
    const float yq = g_Y[src];
    const float yk = g_Y[(long long)BT * Ddim + src];
    const float yv = g_Y[2ll * BT * Ddim + src];
    g_Q[idx] = 1.2f / (1.f + expf(-1.6f * yq));
    g_K[idx] = 1.2f / (1.f + expf(-1.6f * yk));
    g_V[idx] = yv;
}

__global__ void reduceK(const float* __restrict__ src, float* __restrict__ dst)
{
    const int N4 = BE * TDE / 4;
    const int i = blockIdx.x * 256 + threadIdx.x;
    if (i >= N4) return;
    const float4* p = reinterpret_cast<const float4*>(src);
    float4 r = p[i];
#pragma unroll
    for (int s = 1; s < KSPLIT; ++s) {
        float4 a = p[(long long)s * N4 + i];
        r.x += a.x; r.y += a.y; r.z += a.z; r.w += a.w;
    }
    reinterpret_cast<float4*>(dst)[i] = r;
}

__global__ void gather_x()
{
    const int idx = blockIdx.x * 256 + threadIdx.x;
    if (idx >= BT * Ddim) return;
    const int b = idx / (Tdim * Ddim);
    const int rem = idx % (Tdim * Ddim);
    const int t = rem / Ddim, d = rem % Ddim;
    const int g = b * Edim + (d >> 6);
    g_X[idx] = g_O[((long long)g * Tdim + t) * DE + (d & 63)];
}

// ------------------- launch --------------------------------------------------
static inline int smem_sz(int BN, bool TRA, bool TRB)
{
    const int ASZ = TRA ? 32 * 136 : 128 * 40;
    const int BSZ = TRB ? 32 * (BN + 8) : BN * 40;
    const int SAF = TRA ? 32 * 136 : 128 * 36;
    const int SBF = TRB ? 32 * (BN + 8) : BN * 36;
    return (SAF + SBF) * 2 * 4 + (ASZ + BSZ) * 2 * 2;
}

extern "C" void kernel_launch(void* const* d_in, const int* in_sizes, int n_in,
                              void* d_out, int out_size)
{
    const float* input  = (const float*)d_in[0];
    const float* Wq     = (const float*)d_in[1];
    const float* bq     = (const float*)d_in[2];
    const float* Wk     = (const float*)d_in[3];
    const float* bk     = (const float*)d_in[4];
    const float* Wv     = (const float*)d_in[5];
    const float* bv     = (const float*)d_in[6];
    const float* Wo     = (const float*)d_in[7];
    const float* bo     = (const float*)d_in[8];
    const float* punish = (const float*)d_in[9];
    const float* orth   = (const float*)d_in[10];
    float* out = (float*)d_out;

    float *Y, *Wcat, *bcat, *Q, *Kp, *V, *W2p, *W2, *S, *Op, *O, *X;
    cudaGetSymbolAddress((void**)&Y,    g_Y);
    cudaGetSymbolAddress((void**)&Wcat, g_Wcat);
    cudaGetSymbolAddress((void**)&bcat, g_bcat);
    cudaGetSymbolAddress((void**)&Q,    g_Q);
    cudaGetSymbolAddress((void**)&Kp,   g_K);
    cudaGetSymbolAddress((void**)&V,    g_V);
    cudaGetSymbolAddress((void**)&W2p,  g_W2p);
    cudaGetSymbolAddress((void**)&W2,   g_W2);
    cudaGetSymbolAddress((void**)&S,    g_S);
    cudaGetSymbolAddress((void**)&Op,   g_Op);
    cudaGetSymbolAddress((void**)&O,    g_O);
    cudaGetSymbolAddress((void**)&X,    g_X);

    const float inv_sqrt_T = 1.0f / sqrtf((float)Tdim);
    const int WW = Ddim * Ddim;

    const int SM_P  = smem_sz(128, false, false);
    const int SM_W2 = smem_sz(64,  true,  true);
    const int SM_O  = smem_sz(64,  false, true);

    cudaFuncSetAttribute(mma_gemm<128, 0, 0, 1, 0>,
                         cudaFuncAttributeMaxDynamicSharedMemorySize, SM_P);
    cudaFuncSetAttribute(mma_gemm<128, 0, 0, 2, 0>,
                         cudaFuncAttributeMaxDynamicSharedMemorySize, SM_P);
    cudaFuncSetAttribute(mma_gemm<64, 1, 1, 3, 1>,
                         cudaFuncAttributeMaxDynamicSharedMemorySize, SM_W2);
    cudaFuncSetAttribute(mma_gemm<64, 0, 1, 3, 0>,
                         cudaFuncAttributeMaxDynamicSharedMemorySize, SM_O);

    const int kPer = (((Tdim + 31) / 32) + KSPLIT - 1) / KSPLIT;   // 7

    // 0) pack Q/K/V weights
    pack_wb<<<(WW + 255) / 256, 256>>>(Wq, Wk, Wv, bq, bk, bv);

    // 1) projections: Y[z] = input @ W[z]^T + b[z]
    mma_gemm<128, 0, 0, 1, 0><<<dim3(4, 26, 3), 256, SM_P>>>(
        input, Wcat, Y, BT, Ddim, Ddim, Ddim, Ddim, Ddim,
        0ll, (long long)WW, (long long)BT * Ddim, bcat, (long long)Ddim, 0.f, 0, 0ll);

    // 2) reshape + sigmoid
    scatter_qkv<<<(BE * TDE + 255) / 256, 256>>>();

    // 3) W2 partials = orth^T @ V  (split-K x8, vectorized odd-stride loader)
    mma_gemm<64, 1, 1, 3, 1><<<dim3(KSPLIT, 13, BE), 256, SM_W2>>>(
        orth, V, W2p, Tdim, DE, Tdim, Tdim, DE, DE,
        TT, (long long)TDE, (long long)TDE, nullptr, 0ll, 0.f,
        kPer, (long long)BE * TDE);
    reduceK<<<(BE * TDE / 4 + 255) / 256, 256>>>(W2p, W2);

    // 4) S = (Q K^T) * scale * punish  -> fp32, padded stride TSP
    mma_gemm<128, 0, 0, 2, 0><<<dim3(13, 13, BE), 256, SM_P>>>(
        Q, Kp, S, Tdim, Tdim, DE, DE, DE, TSP,
        (long long)TDE, (long long)TDE, (long long)Tdim * TSP,
        punish, 0ll, inv_sqrt_T, 0, 0ll);

    // 5) O partials = S @ W2  (split-K x8), reduce
    mma_gemm<64, 0, 1, 3, 0><<<dim3(KSPLIT, 13, BE), 256, SM_O>>>(
        S, W2, Op, Tdim, DE, Tdim, TSP, DE, DE,
        (long long)Tdim * TSP, (long long)TDE, (long long)TDE, nullptr, 0ll, 0.f,
        kPer, (long long)BE * TDE);
    reduceK<<<(BE * TDE / 4 + 255) / 256, 256>>>(Op, O);

    // 6) inverse reshape
    gather_x<<<(BT * Ddim + 255) / 256, 256>>>();

    // 7) out = X @ Wo^T + bo
    mma_gemm<128, 0, 0, 1, 0><<<dim3(4, 26, 1), 256, SM_P>>>(
        X, Wo, out, BT, Ddim, Ddim, Ddim, Ddim, Ddim,
        0ll, 0ll, 0ll, bo, 0ll, 0.f, 0, 0ll);
}

// round 16
// speedup vs baseline: 1.0604x; 1.0604x over previous
#include <cuda_runtime.h>
#include <math.h>
#include <stdint.h>

#define Tdim 1653
#define TSP  1664
#define Ddim 512
#define Bdim 2
#define Edim 8
#define DE 64
#define BE 16
#define BT 3306
#define TDE (Tdim * DE)
#define KSPLIT 8
static const long long TT = (long long)Tdim * Tdim;

// ------------------- device scratch ------------------------------------------
__device__ __align__(16) float g_Y[3 * BT * Ddim];
__device__ __align__(16) float g_Wcat[3 * Ddim * Ddim];
__device__ __align__(16) float g_bcat[3 * Ddim];
__device__ __align__(16) float g_Q[BE * TDE], g_K[BE * TDE], g_V[BE * TDE];
__device__ __align__(16) float g_W2p[KSPLIT * BE * TDE];
__device__ __align__(16) float g_W2[BE * TDE];
__device__ __align__(16) float g_S[(long long)BE * Tdim * TSP];
__device__ __align__(16) float g_Op[KSPLIT * BE * TDE];
__device__ __align__(16) float g_O[BE * TDE];
__device__ __align__(16) float g_X[BT * Ddim];

// ------------------- helpers -------------------------------------------------
__device__ __forceinline__ uint32_t smem_u32(const void* p) {
    uint32_t a;
    asm("{ .reg .u64 t; cvta.to.shared.u64 t, %1; cvt.u32.u64 %0, t; }"
        : "=r"(a) : "l"(p));
    return a;
}
__device__ __forceinline__ uint32_t f2tf(float v) {
    uint32_t r;
    asm("cvt.rna.tf32.f32 %0, %1;" : "=r"(r) : "f"(v));
    return r;
}
__device__ __forceinline__ void mma_tf32(float* d, const uint32_t* a, const uint32_t* b) {
    asm volatile("mma.sync.aligned.m16n8k8.row.col.f32.tf32.tf32.f32 "
        "{%0,%1,%2,%3}, {%4,%5,%6,%7}, {%8,%9}, {%0,%1,%2,%3};"
        : "+f"(d[0]), "+f"(d[1]), "+f"(d[2]), "+f"(d[3])
        : "r"(a[0]), "r"(a[1]), "r"(a[2]), "r"(a[3]), "r"(b[0]), "r"(b[1]));
}
__device__ __forceinline__ void cpa16(float* d, const float* s) {
    asm volatile("cp.async.ca.shared.global [%0], [%1], 16;"
                 :: "r"(smem_u32(d)), "l"(s));
}
__device__ __forceinline__ void cpa4(float* d, const float* s) {
    asm volatile("cp.async.ca.shared.global [%0], [%1], 4;"
                 :: "r"(smem_u32(d)), "l"(s));
}
__device__ __forceinline__ int falign(const float* p) {
    return (int)((((uintptr_t)p) >> 2) & 3);
}

// ---- cp.async prefetchers: fp32 gmem -> fp32 staging smem ----
// no-trans: 128 rows x 32 k, staging pitch 36
__device__ __forceinline__ void pf_nt(const float* __restrict__ src, int r0, int Rtot,
                                      int ld, int k0, int K, float* st)
{
    const int t = threadIdx.x;
    const int r = t >> 1, h = t & 1;
    const int kb = k0 + h * 16;
    float* d = st + r * 36 + h * 16;
    const float* s = src + (long long)(r0 + r) * ld + kb;
    if ((r0 + r) < Rtot) {
        const uint32_t da = smem_u32(d);
#pragma unroll
        for (int q = 0; q < 4; ++q) {
            const int rem = (K - (kb + q * 4)) * 4;
            if (rem >= 16) {
                asm volatile("cp.async.ca.shared.global [%0], [%1], 16;"
                             :: "r"(da + q * 16), "l"(s + q * 4));
            } else if (rem > 0) {
                asm volatile("cp.async.ca.shared.global [%0], [%1], 16, %2;"
                             :: "r"(da + q * 16), "l"(s + q * 4), "r"(rem));
            } else {
                *reinterpret_cast<float4*>(d + q * 4) = make_float4(0.f, 0.f, 0.f, 0.f);
            }
        }
    } else {
#pragma unroll
        for (int q = 0; q < 4; ++q)
            *reinterpret_cast<float4*>(d + q * 4) = make_float4(0.f, 0.f, 0.f, 0.f);
    }
}

// trans, vectorized: 32 k-rows x C cols, pitch C+8; element c at smem a+c
// where a = TRUE gmem pointer alignment (incl. batch base). 8 threads/row.
template <int C, int ODD>
__device__ __forceinline__ void pf_tr(const float* __restrict__ src, int k0, int K,
                                      int c0, int Ctot, int ld, float* st)
{
    constexpr int PS = C + 8;
    const int t = threadIdx.x;
    const int kr = t >> 3;
    const int lane8 = t & 7;
    float* drow = st + kr * PS;
    const float* g = src + (long long)(k0 + kr) * ld + c0;
    const int a = ODD ? falign(g) : 0;
    const bool rowok = (k0 + kr) < K;
    if (rowok && c0 + C <= Ctot) {
        const int pad = (4 - a) & 3;
        const int nch = (C - pad) >> 2;
        if (ODD && lane8 == 0) {
            for (int q = 0; q < pad; ++q) cpa4(drow + a + q, g + q);
        }
        for (int ch = lane8; ch < nch; ch += 8)
            cpa16(drow + a + pad + ch * 4, g + pad + ch * 4);
        if (ODD && lane8 == 7) {
            for (int q = pad + nch * 4; q < C; ++q) cpa4(drow + a + q, g + q);
        }
    } else {
        for (int c = lane8; c < C; c += 8) {
            if (rowok && c0 + c < Ctot) cpa4(drow + a + c, g + c);
            else                        drow[a + c] = 0.f;
        }
    }
}

// ------------------- 3xTF32 pipelined tensor-core GEMM -----------------------
// C[M,N] = A[M,K]*B^T (logical). TRA: A stored [k][m]; TRB: B stored [k][n].
// ODDA: A rows can be arbitrarily (un)aligned (per-row alignment handling).
// MODE 1: +bias ep[n]  MODE 2: *scale*ep[m*Tdim+n]  MODE 3: split-K partial
template <int BN, int TRA, int TRB, int MODE, int ODDA>
__global__ void __launch_bounds__(256, (BN == 64) ? 3 : 2)
mma_gemm(const float* __restrict__ A, const float* __restrict__ B,
         float* __restrict__ C, int M, int N, int K,
         int lda, int ldb, int ldc,
         long long sA, long long sB, long long sC,
         const float* __restrict__ ep, long long sEp, float scale,
         int kItersPer, long long sKS)
{
    constexpr int PAS = TRA ? 136 : 36;
    constexpr int PBS = TRB ? (BN + 8) : 36;
    constexpr int SAF = TRA ? 32 * 136 : 128 * 36;
    constexpr int SBF = TRB ? 32 * (BN + 8) : BN * 36;

    extern __shared__ __align__(16) float smf[];
    float* stA0 = smf;
    float* stA1 = stA0 + SAF;
    float* stB0 = stA1 + SAF;
    float* stB1 = stB0 + SBF;

    const int bz = blockIdx.z;
    A += (long long)bz * sA;
    B += (long long)bz * sB;
    C += (long long)bz * sC;
    if (MODE == 3) C += (long long)blockIdx.x * sKS;
    if (MODE == 1 || MODE == 2) ep += (long long)bz * sEp;

    const int m0 = blockIdx.y * 128;
    const int n0 = (MODE == 3) ? 0 : blockIdx.x * BN;
    const int tid = threadIdx.x, l = tid & 31, wid = tid >> 5;
    constexpr int WN = BN / 2;
    constexpr int NT = WN / 8;
    const int wm = wid & 3, wn = wid >> 2;
    const int rmw = wm * 32;
    const int nbw = wn * WN;
    const int gid = l >> 2, tig = l & 3;

    float acc[2][NT][4];
#pragma unroll
    for (int i = 0; i < 2; ++i)
#pragma unroll
        for (int j = 0; j < NT; ++j)
#pragma unroll
            for (int q = 0; q < 4; ++q) acc[i][j][q] = 0.f;

    const int kItersAll = (K + 31) / 32;
    int kt0 = 0, kt1 = kItersAll;
    if (MODE == 3) {
        kt0 = blockIdx.x * kItersPer;
        kt1 = min(kItersAll, kt0 + kItersPer);
    }

    auto prefetch = [&](int kt, int buf) {
        const int k0 = kt * 32;
        float* sa = buf ? stA1 : stA0;
        float* sb = buf ? stB1 : stB0;
        if (TRA) pf_tr<128, ODDA>(A, k0, K, m0, M, lda, sa);
        else     pf_nt(A, m0, M, lda, k0, K, sa);
        if (TRB) pf_tr<BN, 0>(B, k0, K, n0, N, ldb, sb);
        else     pf_nt(B, n0, N, ldb, k0, K, sb);
        asm volatile("cp.async.commit_group;" ::: "memory");
    };

    if (kt0 < kt1) {
        prefetch(kt0, 0);
        for (int kt = kt0; kt < kt1; ++kt) {
            const int cur = (kt - kt0) & 1;
            const int k0 = kt * 32;
            if (kt + 1 < kt1) {
                prefetch(kt + 1, cur ^ 1);
                asm volatile("cp.async.wait_group 1;" ::: "memory");
            } else {
                asm volatile("cp.async.wait_group 0;" ::: "memory");
            }
            __syncthreads();
            const float* sa = cur ? stA1 : stA0;
            const float* sb = cur ? stB1 : stB0;
            int fbase = 0;
            if (TRA && ODDA)
                fbase = (int)((falign(A) + (((long long)k0 * lda + m0) & 3)) & 3);
#pragma unroll
            for (int ks = 0; ks < 4; ++ks) {
                const int ka = ks * 8 + tig;
                uint32_t ah[2][4], al[2][4];
#pragma unroll
                for (int mt = 0; mt < 2; ++mt) {
                    const int mr = rmw + mt * 16 + gid;
                    float v[4];
                    if (TRA) {
                        const int o0 = ODDA ? ((fbase + ka * (lda & 3)) & 3) : 0;
                        const int o1 = ODDA ? ((fbase + (ka + 4) * (lda & 3)) & 3) : 0;
                        v[0] = sa[ka * PAS + o0 + mr];
                        v[1] = sa[ka * PAS + o0 + mr + 8];
                        v[2] = sa[(ka + 4) * PAS + o1 + mr];
                        v[3] = sa[(ka + 4) * PAS + o1 + mr + 8];
                    } else {
                        v[0] = sa[mr * PAS + ka];
                        v[1] = sa[(mr + 8) * PAS + ka];
                        v[2] = sa[mr * PAS + ka + 4];
                        v[3] = sa[(mr + 8) * PAS + ka + 4];
                    }
#pragma unroll
                    for (int q = 0; q < 4; ++q) {
                        ah[mt][q] = f2tf(v[q]);
                        al[mt][q] = __float_as_uint(v[q] - __uint_as_float(ah[mt][q]));
                    }
                }
#pragma unroll
                for (int nt = 0; nt < NT; ++nt) {
                    const int nr = nbw + nt * 8 + gid;
                    float w0, w1;
                    if (TRB) { w0 = sb[ka * PBS + nr]; w1 = sb[(ka + 4) * PBS + nr]; }
                    else     { w0 = sb[nr * PBS + ka]; w1 = sb[nr * PBS + ka + 4]; }
                    uint32_t bh[2], bl[2];
                    bh[0] = f2tf(w0); bl[0] = __float_as_uint(w0 - __uint_as_float(bh[0]));
                    bh[1] = f2tf(w1); bl[1] = __float_as_uint(w1 - __uint_as_float(bh[1]));
#pragma unroll
                    for (int mt = 0; mt < 2; ++mt) {
                        mma_tf32(acc[mt][nt], ah[mt], bh);
                        mma_tf32(acc[mt][nt], al[mt], bh);
                        mma_tf32(acc[mt][nt], ah[mt], bl);
                    }
                }
            }
            __syncthreads();
        }
    }

#pragma unroll
    for (int mt = 0; mt < 2; ++mt)
#pragma unroll
        for (int nt = 0; nt < NT; ++nt)
#pragma unroll
            for (int half = 0; half < 2; ++half) {
                const int m = m0 + rmw + mt * 16 + (l >> 2) + half * 8;
                const int n = n0 + nbw + nt * 8 + (l & 3) * 2;
                if (m >= M) continue;
                float v0 = acc[mt][nt][half * 2 + 0];
                float v1 = acc[mt][nt][half * 2 + 1];
                if (MODE == 1) {
                    if (n < N)     v0 += ep[n];
                    if (n + 1 < N) v1 += ep[n + 1];
                }
                if (MODE == 2) {
                    if (n < N)     v0 *= scale * ep[(long long)m * Tdim + n];
                    if (n + 1 < N) v1 *= scale * ep[(long long)m * Tdim + n + 1];
                }
                if (n + 1 < N) {
                    *reinterpret_cast<float2*>(C + (long long)m * ldc + n) = make_float2(v0, v1);
                } else if (n < N) {
                    C[(long long)m * ldc + n] = v0;
                }
            }
}

// ------------------- elementwise kernels -------------------------------------
__global__ void pack_wb(const float* Wq, const float* Wk, const float* Wv,
                        const float* bq, const float* bk, const float* bv)
{
    const int i = blockIdx.x * 256 + threadIdx.x;
    const int WW = Ddim * Ddim;
    if (i < WW) {
        g_Wcat[i] = Wq[i];
        g_Wcat[WW + i] = Wk[i];
        g_Wcat[2 * WW + i] = Wv[i];
    }
    if (i < Ddim) {
        g_bcat[i] = bq[i];
        g_bcat[Ddim + i] = bk[i];
        g_bcat[2 * Ddim + i] = bv[i];
    }
}

__global__ void scatter_qkv()
{
    const int idx = blockIdx.x * 256 + threadIdx.x;
    if (idx >= BE * TDE) return;
    const int g = idx / TDE, f = idx % TDE;
    const int b = g >> 3, e = g & 7;
    const int tt = f % Tdim, j = f / Tdim;
    const long long src = (long long)(b * Tdim + tt) * Ddim + e * DE + j;
    const float yq = g_Y[src];
    const float yk = g_Y[(long long)BT * Ddim + src];
    const float yv = g_Y[2ll * BT * Ddim + src];
    g_Q[idx] = 1.2f / (1.f + expf(-1.6f * yq));
    g_K[idx] = 1.2f / (1.f + expf(-1.6f * yk));
    g_V[idx] = yv;
}

__global__ void reduceK(const float* __restrict__ src, float* __restrict__ dst)
{
    const int N4 = BE * TDE / 4;
    const int i = blockIdx.x * 256 + threadIdx.x;
    if (i >= N4) return;
    const float4* p = reinterpret_cast<const float4*>(src);
    float4 r = p[i];
#pragma unroll
    for (int s = 1; s < KSPLIT; ++s) {
        float4 a = p[(long long)s * N4 + i];
        r.x += a.x; r.y += a.y; r.z += a.z; r.w += a.w;
    }
    reinterpret_cast<float4*>(dst)[i] = r;
}

__global__ void gather_x()
{
    const int idx = blockIdx.x * 256 + threadIdx.x;
    if (idx >= BT * Ddim) return;
    const int b = idx / (Tdim * Ddim);
    const int rem = idx % (Tdim * Ddim);
    const int t = rem / Ddim, d = rem % Ddim;
    const int g = b * Edim + (d >> 6);
    g_X[idx] = g_O[((long long)g * Tdim + t) * DE + (d & 63)];
}

// ------------------- launch --------------------------------------------------
static inline int smem_sz(int BN, bool TRA, bool TRB)
{
    const int SAF = TRA ? 32 * 136 : 128 * 36;
    const int SBF = TRB ? 32 * (BN + 8) : BN * 36;
    return (SAF + SBF) * 2 * 4;
}

extern "C" void kernel_launch(void* const* d_in, const int* in_sizes, int n_in,
                              void* d_out, int out_size)
{
    const float* input  = (const float*)d_in[0];
    const float* Wq     = (const float*)d_in[1];
    const float* bq     = (const float*)d_in[2];
    const float* Wk     = (const float*)d_in[3];
    const float* bk     = (const float*)d_in[4];
    const float* Wv     = (const float*)d_in[5];
    const float* bv     = (const float*)d_in[6];
    const float* Wo     = (const float*)d_in[7];
    const float* bo     = (const float*)d_in[8];
    const float* punish = (const float*)d_in[9];
    const float* orth   = (const float*)d_in[10];
    float* out = (float*)d_out;

    float *Y, *Wcat, *bcat, *Q, *Kp, *V, *W2p, *W2, *S, *Op, *O, *X;
    cudaGetSymbolAddress((void**)&Y,    g_Y);
    cudaGetSymbolAddress((void**)&Wcat, g_Wcat);
    cudaGetSymbolAddress((void**)&bcat, g_bcat);
    cudaGetSymbolAddress((void**)&Q,    g_Q);
    cudaGetSymbolAddress((void**)&Kp,   g_K);
    cudaGetSymbolAddress((void**)&V,    g_V);
    cudaGetSymbolAddress((void**)&W2p,  g_W2p);
    cudaGetSymbolAddress((void**)&W2,   g_W2);
    cudaGetSymbolAddress((void**)&S,    g_S);
    cudaGetSymbolAddress((void**)&Op,   g_Op);
    cudaGetSymbolAddress((void**)&O,    g_O);
    cudaGetSymbolAddress((void**)&X,    g_X);

    const float inv_sqrt_T = 1.0f / sqrtf((float)Tdim);
    const int WW = Ddim * Ddim;

    const int SM_P  = smem_sz(128, false, false);
    const int SM_W2 = smem_sz(64,  true,  true);
    const int SM_O  = smem_sz(64,  false, true);

    cudaFuncSetAttribute(mma_gemm<128, 0, 0, 1, 0>,
                         cudaFuncAttributeMaxDynamicSharedMemorySize, SM_P);
    cudaFuncSetAttribute(mma_gemm<128, 0, 0, 2, 0>,
                         cudaFuncAttributeMaxDynamicSharedMemorySize, SM_P);
    cudaFuncSetAttribute(mma_gemm<64, 1, 1, 3, 1>,
                         cudaFuncAttributeMaxDynamicSharedMemorySize, SM_W2);
    cudaFuncSetAttribute(mma_gemm<64, 0, 1, 3, 0>,
                         cudaFuncAttributeMaxDynamicSharedMemorySize, SM_O);

    const int kPer = (((Tdim + 31) / 32) + KSPLIT - 1) / KSPLIT;   // 7

    // 0) pack Q/K/V weights
    pack_wb<<<(WW + 255) / 256, 256>>>(Wq, Wk, Wv, bq, bk, bv);

    // 1) projections: Y[z] = input @ W[z]^T + b[z]
    mma_gemm<128, 0, 0, 1, 0><<<dim3(4, 26, 3), 256, SM_P>>>(
        input, Wcat, Y, BT, Ddim, Ddim, Ddim, Ddim, Ddim,
        0ll, (long long)WW, (long long)BT * Ddim, bcat, (long long)Ddim, 0.f, 0, 0ll);

    // 2) reshape + sigmoid
    scatter_qkv<<<(BE * TDE + 255) / 256, 256>>>();

    // 3) W2 partials = orth^T @ V  (split-K x8), reduce
    mma_gemm<64, 1, 1, 3, 1><<<dim3(KSPLIT, 13, BE), 256, SM_W2>>>(
        orth, V, W2p, Tdim, DE, Tdim, Tdim, DE, DE,
        TT, (long long)TDE, (long long)TDE, nullptr, 0ll, 0.f,
        kPer, (long long)BE * TDE);
    reduceK<<<(BE * TDE / 4 + 255) / 256, 256>>>(W2p, W2);

    // 4) S = (Q K^T) * scale * punish  -> fp32, padded stride TSP
    mma_gemm<128, 0, 0, 2, 0><<<dim3(13, 13, BE), 256, SM_P>>>(
        Q, Kp, S, Tdim, Tdim, DE, DE, DE, TSP,
        (long long)TDE, (long long)TDE, (long long)Tdim * TSP,
        punish, 0ll, inv_sqrt_T, 0, 0ll);

    // 5) O partials = S @ W2  (split-K x8), reduce
    mma_gemm<64, 0, 1, 3, 0><<<dim3(KSPLIT, 13, BE), 256, SM_O>>>(
        S, W2, Op, Tdim, DE, Tdim, TSP, DE, DE,
        (long long)Tdim * TSP, (long long)TDE, (long long)TDE, nullptr, 0ll, 0.f,
        kPer, (long long)BE * TDE);
    reduceK<<<(BE * TDE / 4 + 255) / 256, 256>>>(Op, O);

    // 6) inverse reshape
    gather_x<<<(BT * Ddim + 255) / 256, 256>>>();

    // 7) out = X @ Wo^T + bo
    mma_gemm<128, 0, 0, 1, 0><<<dim3(4, 26, 1), 256, SM_P>>>(
        X, Wo, out, BT, Ddim, Ddim, Ddim, Ddim, Ddim,
        0ll, 0ll, 0ll, bo, 0ll, 0.f, 0, 0ll);
}

// round 17
// speedup vs baseline: 1.1699x; 1.1033x over previous
#include <cuda_runtime.h>
#include <math.h>
#include <stdint.h>

#define Tdim 1653
#define TSP  1664
#define Ddim 512
#define Bdim 2
#define Edim 8
#define DE 64
#define BE 16
#define BT 3306
#define TDE (Tdim * DE)
#define KSPLIT 8
static const long long TT = (long long)Tdim * Tdim;

// ------------------- device scratch ------------------------------------------
__device__ __align__(16) float g_Y[3 * BT * Ddim];
__device__ __align__(16) float g_Wcat[3 * Ddim * Ddim];
__device__ __align__(16) float g_bcat[3 * Ddim];
__device__ __align__(16) float g_Q[BE * TDE], g_K[BE * TDE], g_V[BE * TDE];
__device__ __align__(16) float g_W2p[KSPLIT * BE * TDE];
__device__ __align__(16) float g_W2[BE * TDE];
__device__ __align__(16) float g_S[(long long)BE * Tdim * TSP];
__device__ __align__(16) float g_Op[KSPLIT * BE * TDE];
__device__ __align__(16) float g_O[BE * TDE];

// ------------------- helpers -------------------------------------------------
__device__ __forceinline__ uint32_t smem_u32(const void* p) {
    uint32_t a;
    asm("{ .reg .u64 t; cvta.to.shared.u64 t, %1; cvt.u32.u64 %0, t; }"
        : "=r"(a) : "l"(p));
    return a;
}
__device__ __forceinline__ uint32_t f2tf(float v) {
    uint32_t r;
    asm("cvt.rna.tf32.f32 %0, %1;" : "=r"(r) : "f"(v));
    return r;
}
__device__ __forceinline__ void mma_tf32(float* d, const uint32_t* a, const uint32_t* b) {
    asm volatile("mma.sync.aligned.m16n8k8.row.col.f32.tf32.tf32.f32 "
        "{%0,%1,%2,%3}, {%4,%5,%6,%7}, {%8,%9}, {%0,%1,%2,%3};"
        : "+f"(d[0]), "+f"(d[1]), "+f"(d[2]), "+f"(d[3])
        : "r"(a[0]), "r"(a[1]), "r"(a[2]), "r"(a[3]), "r"(b[0]), "r"(b[1]));
}
__device__ __forceinline__ void cpa16(float* d, const float* s) {
    asm volatile("cp.async.ca.shared.global [%0], [%1], 16;"
                 :: "r"(smem_u32(d)), "l"(s));
}
__device__ __forceinline__ void cpa4(float* d, const float* s) {
    asm volatile("cp.async.ca.shared.global [%0], [%1], 4;"
                 :: "r"(smem_u32(d)), "l"(s));
}
__device__ __forceinline__ int falign(const float* p) {
    return (int)((((uintptr_t)p) >> 2) & 3);
}

// ---- cp.async prefetchers: fp32 gmem -> fp32 staging smem ----
// no-trans: 128 rows x 32 k, staging pitch 36
__device__ __forceinline__ void pf_nt(const float* __restrict__ src, int r0, int Rtot,
                                      int ld, int k0, int K, float* st)
{
    const int t = threadIdx.x;
    const int r = t >> 1, h = t & 1;
    const int kb = k0 + h * 16;
    float* d = st + r * 36 + h * 16;
    const float* s = src + (long long)(r0 + r) * ld + kb;
    if ((r0 + r) < Rtot) {
        const uint32_t da = smem_u32(d);
#pragma unroll
        for (int q = 0; q < 4; ++q) {
            const int rem = (K - (kb + q * 4)) * 4;
            if (rem >= 16) {
                asm volatile("cp.async.ca.shared.global [%0], [%1], 16;"
                             :: "r"(da + q * 16), "l"(s + q * 4));
            } else if (rem > 0) {
                asm volatile("cp.async.ca.shared.global [%0], [%1], 16, %2;"
                             :: "r"(da + q * 16), "l"(s + q * 4), "r"(rem));
            } else {
                *reinterpret_cast<float4*>(d + q * 4) = make_float4(0.f, 0.f, 0.f, 0.f);
            }
        }
    } else {
#pragma unroll
        for (int q = 0; q < 4; ++q)
            *reinterpret_cast<float4*>(d + q * 4) = make_float4(0.f, 0.f, 0.f, 0.f);
    }
}

// gather variant for out-projection: logical X[m, k] read directly from O.
// m = b*Tdim + t ; X[m, k] = O[((b*8 + k/64)*Tdim + t)*64 + (k%64)].
// 16-float chunks at 16-aligned k stay within one 64-block -> contiguous.
__device__ __forceinline__ void pf_nt_ga(const float* __restrict__ O, int r0,
                                         int k0, float* st)
{
    const int t = threadIdx.x;
    const int r = t >> 1, h = t & 1;
    const int kb = k0 + h * 16;
    float* d = st + r * 36 + h * 16;
    const int m = r0 + r;
    if (m < BT) {
        const int b = (m >= Tdim) ? 1 : 0;
        const int tt = m - b * Tdim;
        const int g = b * Edim + (kb >> 6);
        const float* s = O + ((long long)g * Tdim + tt) * DE + (kb & 63);
        const uint32_t da = smem_u32(d);
#pragma unroll
        for (int q = 0; q < 4; ++q)
            asm volatile("cp.async.ca.shared.global [%0], [%1], 16;"
                         :: "r"(da + q * 16), "l"(s + q * 4));
    } else {
#pragma unroll
        for (int q = 0; q < 4; ++q)
            *reinterpret_cast<float4*>(d + q * 4) = make_float4(0.f, 0.f, 0.f, 0.f);
    }
}

// trans, vectorized: 32 k-rows x C cols, pitch C+8; element c at smem a+c
// where a = TRUE gmem pointer alignment (incl. batch base). 8 threads/row.
template <int C, int ODD>
__device__ __forceinline__ void pf_tr(const float* __restrict__ src, int k0, int K,
                                      int c0, int Ctot, int ld, float* st)
{
    constexpr int PS = C + 8;
    const int t = threadIdx.x;
    const int kr = t >> 3;
    const int lane8 = t & 7;
    float* drow = st + kr * PS;
    const float* g = src + (long long)(k0 + kr) * ld + c0;
    const int a = ODD ? falign(g) : 0;
    const bool rowok = (k0 + kr) < K;
    if (rowok && c0 + C <= Ctot) {
        const int pad = (4 - a) & 3;
        const int nch = (C - pad) >> 2;
        if (ODD && lane8 == 0) {
            for (int q = 0; q < pad; ++q) cpa4(drow + a + q, g + q);
        }
        for (int ch = lane8; ch < nch; ch += 8)
            cpa16(drow + a + pad + ch * 4, g + pad + ch * 4);
        if (ODD && lane8 == 7) {
            for (int q = pad + nch * 4; q < C; ++q) cpa4(drow + a + q, g + q);
        }
    } else {
        for (int c = lane8; c < C; c += 8) {
            if (rowok && c0 + c < Ctot) cpa4(drow + a + c, g + c);
            else                        drow[a + c] = 0.f;
        }
    }
}

// ------------------- 3xTF32 GEMM body ----------------------------------------
// C[M,N] = A[M,K]*B^T (logical). TRA: A stored [k][m]; TRB: B stored [k][n].
// GA: A gathered from O layout. MODE 1: +bias ep[n]  MODE 2: *scale*ep[m*T+n]
// MODE 3: plain partial store.
template <int BN, int TRA, int TRB, int MODE, int ODDA, int GA>
__device__ __forceinline__ void gemm_body(
    const float* __restrict__ A, const float* __restrict__ B,
    float* __restrict__ C, int M, int N, int K,
    int lda, int ldb, int ldc,
    int m0, int n0, int kt0, int kt1,
    const float* __restrict__ ep, float scale, float* smf)
{
    constexpr int PAS = TRA ? 136 : 36;
    constexpr int PBS = TRB ? (BN + 8) : 36;
    constexpr int SAF = TRA ? 32 * 136 : 128 * 36;
    constexpr int SBF = TRB ? 32 * (BN + 8) : BN * 36;

    float* stA0 = smf;
    float* stA1 = stA0 + SAF;
    float* stB0 = stA1 + SAF;
    float* stB1 = stB0 + SBF;

    const int tid = threadIdx.x, l = tid & 31, wid = tid >> 5;
    constexpr int WN = BN / 2;
    constexpr int NT = WN / 8;
    const int wm = wid & 3, wn = wid >> 2;
    const int rmw = wm * 32;
    const int nbw = wn * WN;
    const int gid = l >> 2, tig = l & 3;
    // alignment of fragment rows: constant over the whole kernel since
    // k0*lda = 0 (mod 4) and m0 = 0 (mod 4).
    const int oA = (TRA && ODDA) ? ((falign(A) + tig * (lda & 3)) & 3) : 0;

    float acc[2][NT][4];
#pragma unroll
    for (int i = 0; i < 2; ++i)
#pragma unroll
        for (int j = 0; j < NT; ++j)
#pragma unroll
            for (int q = 0; q < 4; ++q) acc[i][j][q] = 0.f;

    auto prefetch = [&](int kt, int buf) {
        const int k0 = kt * 32;
        float* sa = buf ? stA1 : stA0;
        float* sb = buf ? stB1 : stB0;
        if (GA)       pf_nt_ga(A, m0, k0, sa);
        else if (TRA) pf_tr<128, ODDA>(A, k0, K, m0, M, lda, sa);
        else          pf_nt(A, m0, M, lda, k0, K, sa);
        if (TRB) pf_tr<BN, 0>(B, k0, K, n0, N, ldb, sb);
        else     pf_nt(B, n0, N, ldb, k0, K, sb);
        asm volatile("cp.async.commit_group;" ::: "memory");
    };

    if (kt0 < kt1) {
        prefetch(kt0, 0);
        for (int kt = kt0; kt < kt1; ++kt) {
            const int cur = (kt - kt0) & 1;
            if (kt + 1 < kt1) {
                prefetch(kt + 1, cur ^ 1);
                asm volatile("cp.async.wait_group 1;" ::: "memory");
            } else {
                asm volatile("cp.async.wait_group 0;" ::: "memory");
            }
            __syncthreads();
            const float* sa = cur ? stA1 : stA0;
            const float* sb = cur ? stB1 : stB0;
#pragma unroll
            for (int ks = 0; ks < 4; ++ks) {
                const int ka = ks * 8 + tig;
                uint32_t ah[2][4], al[2][4];
#pragma unroll
                for (int mt = 0; mt < 2; ++mt) {
                    const int mr = rmw + mt * 16 + gid;
                    float v[4];
                    if (TRA) {
                        v[0] = sa[ka * PAS + oA + mr];
                        v[1] = sa[ka * PAS + oA + mr + 8];
                        v[2] = sa[(ka + 4) * PAS + oA + mr];
                        v[3] = sa[(ka + 4) * PAS + oA + mr + 8];
                    } else {
                        v[0] = sa[mr * PAS + ka];
                        v[1] = sa[(mr + 8) * PAS + ka];
                        v[2] = sa[mr * PAS + ka + 4];
                        v[3] = sa[(mr + 8) * PAS + ka + 4];
                    }
#pragma unroll
                    for (int q = 0; q < 4; ++q) {
                        ah[mt][q] = f2tf(v[q]);
                        al[mt][q] = __float_as_uint(v[q] - __uint_as_float(ah[mt][q]));
                    }
                }
#pragma unroll
                for (int nt = 0; nt < NT; ++nt) {
                    const int nr = nbw + nt * 8 + gid;
                    float w0, w1;
                    if (TRB) { w0 = sb[ka * PBS + nr]; w1 = sb[(ka + 4) * PBS + nr]; }
                    else     { w0 = sb[nr * PBS + ka]; w1 = sb[nr * PBS + ka + 4]; }
                    uint32_t bh[2], bl[2];
                    bh[0] = f2tf(w0); bl[0] = __float_as_uint(w0 - __uint_as_float(bh[0]));
                    bh[1] = f2tf(w1); bl[1] = __float_as_uint(w1 - __uint_as_float(bh[1]));
#pragma unroll
                    for (int mt = 0; mt < 2; ++mt) {
                        mma_tf32(acc[mt][nt], ah[mt], bh);
                        mma_tf32(acc[mt][nt], al[mt], bh);
                        mma_tf32(acc[mt][nt], ah[mt], bl);
                    }
                }
            }
            __syncthreads();
        }
    }

#pragma unroll
    for (int mt = 0; mt < 2; ++mt)
#pragma unroll
        for (int nt = 0; nt < NT; ++nt)
#pragma unroll
            for (int half = 0; half < 2; ++half) {
                const int m = m0 + rmw + mt * 16 + (l >> 2) + half * 8;
                const int n = n0 + nbw + nt * 8 + (l & 3) * 2;
                if (m >= M) continue;
                float v0 = acc[mt][nt][half * 2 + 0];
                float v1 = acc[mt][nt][half * 2 + 1];
                if (MODE == 1) {
                    if (n < N)     v0 += ep[n];
                    if (n + 1 < N) v1 += ep[n + 1];
                }
                if (MODE == 2) {
                    if (n < N)     v0 *= scale * ep[(long long)m * Tdim + n];
                    if (n + 1 < N) v1 *= scale * ep[(long long)m * Tdim + n + 1];
                }
                if (n + 1 < N) {
                    *reinterpret_cast<float2*>(C + (long long)m * ldc + n) = make_float2(v0, v1);
                } else if (n < N) {
                    C[(long long)m * ldc + n] = v0;
                }
            }
}

// ------------------- generic GEMM global -------------------------------------
template <int BN, int TRA, int TRB, int MODE, int ODDA, int GA>
__global__ void __launch_bounds__(256, (BN == 64) ? 3 : 2)
mma_gemm(const float* __restrict__ A, const float* __restrict__ B,
         float* __restrict__ C, int M, int N, int K,
         int lda, int ldb, int ldc,
         long long sA, long long sB, long long sC,
         const float* __restrict__ ep, long long sEp, float scale,
         int kItersPer, long long sKS)
{
    extern __shared__ __align__(16) float smf[];
    const int bz = blockIdx.z;
    A += (long long)bz * sA;
    B += (long long)bz * sB;
    C += (long long)bz * sC;
    if (MODE == 3) C += (long long)blockIdx.x * sKS;
    if (MODE == 1 || MODE == 2) ep += (long long)bz * sEp;

    const int m0 = blockIdx.y * 128;
    const int n0 = (MODE == 3) ? 0 : blockIdx.x * BN;
    const int kItersAll = (K + 31) / 32;
    int kt0 = 0, kt1 = kItersAll;
    if (MODE == 3) {
        kt0 = blockIdx.x * kItersPer;
        kt1 = min(kItersAll, kt0 + kItersPer);
    }
    gemm_body<BN, TRA, TRB, MODE, ODDA, GA>(
        A, B, C, M, N, K, lda, ldb, ldc, m0, n0, kt0, kt1, ep, scale, smf);
}

// ------------------- fused W2-partials + S kernel ----------------------------
// grid (KSPLIT + 13, 13, BE):
//   x < KSPLIT : W2 partial = orth^T @ V (split-K chunk x)
//   x >= KSPLIT: S tile (n-block x-KSPLIT) = (Q K^T) * scale * punish
__global__ void __launch_bounds__(256, 2)
fused_w2_s(const float* __restrict__ orth, const float* __restrict__ punish,
           float* __restrict__ W2p, float scale, int kPer)
{
    extern __shared__ __align__(16) float smf[];
    const int bz = blockIdx.z;
    if ((int)blockIdx.x < KSPLIT) {
        const int kItersAll = (Tdim + 31) / 32;           // 52
        const int kt0 = blockIdx.x * kPer;
        const int kt1 = min(kItersAll, kt0 + kPer);
        gemm_body<64, 1, 1, 3, 1, 0>(
            orth + (long long)bz * TT,
            g_V + (long long)bz * TDE,
            W2p + (long long)blockIdx.x * (BE * (long long)TDE) + (long long)bz * TDE,
            Tdim, DE, Tdim, Tdim, DE, DE,
            blockIdx.y * 128, 0, kt0, kt1, nullptr, 0.f, smf);
    } else {
        gemm_body<128, 0, 0, 2, 0, 0>(
            g_Q + (long long)bz * TDE,
            g_K + (long long)bz * TDE,
            g_S + (long long)bz * Tdim * TSP,
            Tdim, Tdim, DE, DE, DE, TSP,
            blockIdx.y * 128, ((int)blockIdx.x - KSPLIT) * 128, 0, 2,
            punish, scale, smf);
    }
}

// ------------------- elementwise kernels -------------------------------------
__global__ void pack_wb(const float* Wq, const float* Wk, const float* Wv,
                        const float* bq, const float* bk, const float* bv)
{
    const int i = blockIdx.x * 256 + threadIdx.x;
    const int WW = Ddim * Ddim;
    if (i < WW) {
        g_Wcat[i] = Wq[i];
        g_Wcat[WW + i] = Wk[i];
        g_Wcat[2 * WW + i] = Wv[i];
    }
    if (i < Ddim) {
        g_bcat[i] = bq[i];
        g_bcat[Ddim + i] = bk[i];
        g_bcat[2 * Ddim + i] = bv[i];
    }
}

__global__ void scatter_qkv()
{
    const int idx = blockIdx.x * 256 + threadIdx.x;
    if (idx >= BE * TDE) return;
    const int g = idx / TDE, f = idx % TDE;
    const int b = g >> 3, e = g & 7;
    const int tt = f % Tdim, j = f / Tdim;
    const long long src = (long long)(b * Tdim + tt) * Ddim + e * DE + j;
    const float yq = g_Y[src];
    const float yk = g_Y[(long long)BT * Ddim + src];
    const float yv = g_Y[2ll * BT * Ddim + src];
    g_Q[idx] = 1.2f / (1.f + expf(-1.6f * yq));
    g_K[idx] = 1.2f / (1.f + expf(-1.6f * yk));
    g_V[idx] = yv;
}

__global__ void reduceK(const float* __restrict__ src, float* __restrict__ dst)
{
    const int N4 = BE * TDE / 4;
    const int i = blockIdx.x * 256 + threadIdx.x;
    if (i >= N4) return;
    const float4* p = reinterpret_cast<const float4*>(src);
    float4 r = p[i];
#pragma unroll
    for (int s = 1; s < KSPLIT; ++s) {
        float4 a = p[(long long)s * N4 + i];
        r.x += a.x; r.y += a.y; r.z += a.z; r.w += a.w;
    }
    reinterpret_cast<float4*>(dst)[i] = r;
}

// ------------------- launch --------------------------------------------------
static inline int smem_sz(int BN, bool TRA, bool TRB)
{
    const int SAF = TRA ? 32 * 136 : 128 * 36;
    const int SBF = TRB ? 32 * (BN + 8) : BN * 36;
    return (SAF + SBF) * 2 * 4;
}

extern "C" void kernel_launch(void* const* d_in, const int* in_sizes, int n_in,
                              void* d_out, int out_size)
{
    const float* input  = (const float*)d_in[0];
    const float* Wq     = (const float*)d_in[1];
    const float* bq     = (const float*)d_in[2];
    const float* Wk     = (const float*)d_in[3];
    const float* bk     = (const float*)d_in[4];
    const float* Wv     = (const float*)d_in[5];
    const float* bv     = (const float*)d_in[6];
    const float* Wo     = (const float*)d_in[7];
    const float* bo     = (const float*)d_in[8];
    const float* punish = (const float*)d_in[9];
    const float* orth   = (const float*)d_in[10];
    float* out = (float*)d_out;

    float *Y, *Wcat, *bcat, *W2p, *W2, *S, *Op, *O;
    cudaGetSymbolAddress((void**)&Y,    g_Y);
    cudaGetSymbolAddress((void**)&Wcat, g_Wcat);
    cudaGetSymbolAddress((void**)&bcat, g_bcat);
    cudaGetSymbolAddress((void**)&W2p,  g_W2p);
    cudaGetSymbolAddress((void**)&W2,   g_W2);
    cudaGetSymbolAddress((void**)&S,    g_S);
    cudaGetSymbolAddress((void**)&Op,   g_Op);
    cudaGetSymbolAddress((void**)&O,    g_O);

    const float inv_sqrt_T = 1.0f / sqrtf((float)Tdim);
    const int WW = Ddim * Ddim;

    const int SM_P = smem_sz(128, false, false);   // 73728
    const int SM_O = smem_sz(64,  false, true);    // 55296
    const int SM_F = SM_P;                         // fused: max of both paths

    cudaFuncSetAttribute(mma_gemm<128, 0, 0, 1, 0, 0>,
                         cudaFuncAttributeMaxDynamicSharedMemorySize, SM_P);
    cudaFuncSetAttribute(mma_gemm<128, 0, 0, 1, 0, 1>,
                         cudaFuncAttributeMaxDynamicSharedMemorySize, SM_P);
    cudaFuncSetAttribute(mma_gemm<64, 0, 1, 3, 0, 0>,
                         cudaFuncAttributeMaxDynamicSharedMemorySize, SM_O);
    cudaFuncSetAttribute(fused_w2_s,
                         cudaFuncAttributeMaxDynamicSharedMemorySize, SM_F);

    const int kPer = (((Tdim + 31) / 32) + KSPLIT - 1) / KSPLIT;   // 7

    // 0) pack Q/K/V weights
    pack_wb<<<(WW + 255) / 256, 256>>>(Wq, Wk, Wv, bq, bk, bv);

    // 1) projections: Y[z] = input @ W[z]^T + b[z]
    mma_gemm<128, 0, 0, 1, 0, 0><<<dim3(4, 26, 3), 256, SM_P>>>(
        input, Wcat, Y, BT, Ddim, Ddim, Ddim, Ddim, Ddim,
        0ll, (long long)WW, (long long)BT * Ddim, bcat, (long long)Ddim, 0.f, 0, 0ll);

    // 2) reshape + sigmoid
    scatter_qkv<<<(BE * TDE + 255) / 256, 256>>>();

    // 3+4) FUSED: W2 partials (split-K x8) and S (QK^T * scale * punish)
    fused_w2_s<<<dim3(KSPLIT + 13, 13, BE), 256, SM_F>>>(
        orth, punish, W2p, inv_sqrt_T, kPer);
    reduceK<<<(BE * TDE / 4 + 255) / 256, 256>>>(W2p, W2);

    // 5) O partials = S @ W2  (split-K x8), reduce
    mma_gemm<64, 0, 1, 3, 0, 0><<<dim3(KSPLIT, 13, BE), 256, SM_O>>>(
        S, W2, Op, Tdim, DE, Tdim, TSP, DE, DE,
        (long long)Tdim * TSP, (long long)TDE, (long long)TDE, nullptr, 0ll, 0.f,
        kPer, (long long)BE * TDE);
    reduceK<<<(BE * TDE / 4 + 255) / 256, 256>>>(Op, O);

    // 6) out = X @ Wo^T + bo   (X gathered directly from O layout)
    mma_gemm<128, 0, 0, 1, 0, 1><<<dim3(4, 26, 1), 256, SM_P>>>(
        O, Wo, out, BT, Ddim, Ddim, Ddim, Ddim, Ddim,
        0ll, 0ll, 0ll, bo, 0ll, 0.f, 0, 0ll);
}